// round 14
// baseline (speedup 1.0000x reference)
#include <cuda_runtime.h>
#include <cstdint>

// Problem constants
#define BB   2048
#define HH   2048
#define RNK  64
#define LL   32

#define NKG  32          // split-K groups for GEMM1 (k per block = 64)
#define KCH  64
#define MT   64          // M tile (samples)
#define HT   64          // h tile for GEMM2
#define TPB  256         // 8 warps everywhere
#define STZ  68          // sample-major tiles stride (68 mod 32 == 4)
#define STB  72          // k-major v tile stride     (72 mod 32 == 8)
#define STU  68          // n-major u/proj stride     (68 mod 32 == 4)

#define PROJ_BLOCKS (NKG * LL)        // 1024
#define OUT_BLOCKS  ((HH / HT) * LL)  // 1024
#define GRID_TOTAL  (1 + PROJ_BLOCKS + OUT_BLOCKS)  // 2049

// Scratch (device globals — no allocations allowed).
// Synchronization state is MONOTONIC across graph replays (epoch-versioned).
__device__ int    g_offsets[LL + 1];
__device__ int    g_sorted[BB];
__device__ float  g_partial[(size_t)NKG * BB * RNK];   // 16 MB, by sorted pos
__device__ float  g_proj[(size_t)BB * RNK];            // by sorted pos
__device__ int    g_epoch    = 0;
__device__ int    g_sortflag = 0;      // holds epoch when sort complete
__device__ int    g_done[LL]  = {};    // monotonic: (E+1)*NKG when layer proj done
__device__ int    g_rdone[LL] = {};    // monotonic
__device__ int    g_flag[LL]  = {};    // holds epoch when layer proj+reduce done
__device__ int    g_allcnt   = 0;      // monotonic

#define MMA_TF32(c0,c1,c2,c3,a0,a1,a2,a3,b0,b1)                         \
    asm("mma.sync.aligned.m16n8k8.row.col.f32.tf32.tf32.f32 "           \
        "{%0,%1,%2,%3}, {%4,%5,%6,%7}, {%8,%9}, {%0,%1,%2,%3};"         \
        : "+f"(c0), "+f"(c1), "+f"(c2), "+f"(c3)                        \
        : "r"(a0), "r"(a1), "r"(a2), "r"(a3), "r"(b0), "r"(b1))

__device__ __forceinline__ void cpa16(uint32_t dst, const void* src, uint32_t sz) {
    asm volatile("cp.async.cg.shared.global [%0], [%1], 16, %2;"
                 :: "r"(dst), "l"(src), "r"(sz));
}
__device__ __forceinline__ void cpa_commit() { asm volatile("cp.async.commit_group;"); }
__device__ __forceinline__ void cpa_wait0()  { asm volatile("cp.async.wait_group 0;"); }

// Low-contention spin: plain L2 load (no RMW), growing backoff.
__device__ __forceinline__ void spin_ge(const int* addr, int target) {
    unsigned ns = 64;
    while (__ldcg(addr) < target) {
        __nanosleep(ns);
        if (ns < 1024) ns <<= 1;
    }
}

// ---------------------------------------------------------------------------
// Single fused kernel, PIPELINED bid schedule:
//   bid 0                         : sort block
//   bid' = bid-1:
//     [0, 32)                     : proj(layer 0,  kg = bid')
//     [32, 2016), q = bid'-32,
//        g = q/64, i = q%64       : i<32 -> proj(layer g+1, kg=i)
//                                   i>=32 -> out(layer g, hb=i-32)
//     [2016, 2048)                : out(layer 31, hb = bid'-2016)
// Every out(l) bid > every proj(l) bid -> deadlock-free; co-resident waves
// contain proj(l+1) and out(l) -> phases overlap layer-by-layer.
// ---------------------------------------------------------------------------
__global__ __launch_bounds__(TPB, 3) void fused_kernel(const float* __restrict__ z,
                                                       const int*   __restrict__ ids,
                                                       const float* __restrict__ v,
                                                       const float* __restrict__ u,
                                                       float* __restrict__ out) {
    extern __shared__ __align__(16) uint32_t smem[];
    __shared__ int s_E;

    int t = threadIdx.x, lane = t & 31, w = t >> 5;
    int gid = lane >> 2, tig = lane & 3;
    int wm = w & 1, wn = w >> 1;           // 8 warps: m32 x n16
    int bid = blockIdx.x;

    if (t == 0) s_E = __ldcg(&g_epoch);
    __syncthreads();
    const int E = s_E;

    // role decode
    int is_sort = (bid == 0);
    int is_proj = 0, l = 0, sub = 0;
    if (!is_sort) {
        int b = bid - 1;
        if (b < 32)            { is_proj = 1; l = 0;  sub = b; }
        else if (b < 2016)     { int q = b - 32; int g = q >> 6; int i = q & 63;
                                 if (i < 32) { is_proj = 1; l = g + 1; sub = i; }
                                 else        { is_proj = 0; l = g;     sub = i - 32; } }
        else                   { is_proj = 0; l = 31; sub = b - 2016; }
    }

    if (is_sort) {
        // ================= SORT =================
        int* A = (int*)smem;               // [LL*256] 32 KB
        int* S = A + LL * 256;             // [256]
        #pragma unroll
        for (int ll2 = 0; ll2 < LL; ll2++) A[ll2 * 256 + t] = 0;
        int seg = t * (BB / 256);
        #pragma unroll
        for (int i = 0; i < BB / 256; i++) {
            int lid = ids[seg + i];
            A[lid * 256 + t]++;
        }
        __syncthreads();
        int base = t * 32;
        int sum = 0;
        #pragma unroll
        for (int j = 0; j < 32; j++) { int x = A[base + j]; A[base + j] = sum; sum += x; }
        S[t] = sum;
        int mysum = sum;
        __syncthreads();
        for (int d = 1; d < 256; d <<= 1) {
            int add = (t >= d) ? S[t - d] : 0;
            __syncthreads();
            S[t] += add;
            __syncthreads();
        }
        int excl = S[t] - mysum;
        #pragma unroll
        for (int j = 0; j < 32; j++) A[base + j] += excl;
        __syncthreads();
        if (t < LL) g_offsets[t] = A[t * 256];
        if (t == 0) g_offsets[LL] = BB;
        #pragma unroll
        for (int i = 0; i < BB / 256; i++) {
            int s = seg + i;
            int lid = ids[s];
            int p = A[lid * 256 + t];
            A[lid * 256 + t] = p + 1;
            g_sorted[p] = s;
        }
        __threadfence();
        __syncthreads();
        if (t == 0) atomicExch(&g_sortflag, E + 1);
    } else if (is_proj) {
        // ================= PROJ =================
        int kg = sub;
        int k0 = kg * KCH;
        uint32_t* sz = smem;               // [MT][STZ]  17.4 KB
        uint32_t* sv = smem + MT * STZ;    // [KCH][STB] 18.4 KB
        uint32_t sz_b = (uint32_t)__cvta_generic_to_shared(sz);
        uint32_t sv_b = (uint32_t)__cvta_generic_to_shared(sv);

        // stage v tile FIRST (independent of the sort), overlaps the spin
        #pragma unroll
        for (int i = 0; i < (KCH * 16) / TPB; i++) {    // 4 iters
            int idx = t + i * TPB;
            int row = idx >> 4, c4 = idx & 15;
            cpa16(sv_b + (row * STB + c4 * 4) * 4,
                  v + ((size_t)l * HH + k0 + row) * RNK + c4 * 4, 16);
        }
        cpa_commit();

        // wait for sort (load-poll, no RMW)
        if (t == 0) spin_ge(&g_sortflag, E + 1);
        __syncthreads();
        __threadfence();

        int off = g_offsets[l];
        int cnt = g_offsets[l + 1] - off;

        for (int m0 = 0; m0 < cnt; m0 += MT) {
            int nc = min(MT, cnt - m0);
            if (m0 > 0) __syncthreads();   // z smem free from previous iteration
            #pragma unroll
            for (int i = 0; i < (MT * 16) / TPB; i++) {     // 4 iters
                int idx = t + i * TPB;
                int row = idx >> 4, c4 = idx & 15;
                const float* src = z;
                uint32_t szb = 0;
                if (row < nc) {
                    int gs = g_sorted[off + m0 + row];
                    src = z + (size_t)gs * HH + k0 + c4 * 4;
                    szb = 16;
                }
                cpa16(sz_b + (row * STZ + c4 * 4) * 4, src, szb);
            }
            cpa_commit();
            cpa_wait0();                    // first iter also covers v
            __syncthreads();

            float acc[2][2][4];
            #pragma unroll
            for (int mt = 0; mt < 2; mt++)
                #pragma unroll
                for (int j = 0; j < 2; j++)
                    #pragma unroll
                    for (int q = 0; q < 4; q++) acc[mt][j][q] = 0.0f;

            #pragma unroll
            for (int ks = 0; ks < KCH / 8; ks++) {          // 8 iters
                int kb = ks * 8 + tig;
                uint32_t b0[2], b1[2];
                #pragma unroll
                for (int j = 0; j < 2; j++) {
                    int n = wn * 16 + j * 8 + gid;
                    b0[j] = sv[kb * STB + n];
                    b1[j] = sv[(kb + 4) * STB + n];
                }
                #pragma unroll
                for (int mt = 0; mt < 2; mt++) {
                    const uint32_t* zr = sz + (wm * 32 + mt * 16 + gid) * STZ;
                    uint32_t a0 = zr[kb];
                    uint32_t a1 = zr[8 * STZ + kb];
                    uint32_t a2 = zr[kb + 4];
                    uint32_t a3 = zr[8 * STZ + kb + 4];
                    #pragma unroll
                    for (int j = 0; j < 2; j++)
                        MMA_TF32(acc[mt][j][0], acc[mt][j][1], acc[mt][j][2], acc[mt][j][3],
                                 a0, a1, a2, a3, b0[j], b1[j]);
                }
            }

            float* pb2 = g_partial + (size_t)kg * BB * RNK;
            #pragma unroll
            for (int mt = 0; mt < 2; mt++) {
                int rbase = wm * 32 + mt * 16 + gid;
                #pragma unroll
                for (int j = 0; j < 2; j++) {
                    int col = wn * 16 + j * 8 + 2 * tig;
                    if (rbase < nc)
                        *(float2*)&pb2[(size_t)(off + m0 + rbase) * RNK + col] =
                            make_float2(acc[mt][j][0], acc[mt][j][1]);
                    if (rbase + 8 < nc)
                        *(float2*)&pb2[(size_t)(off + m0 + rbase + 8) * RNK + col] =
                            make_float2(acc[mt][j][2], acc[mt][j][3]);
                }
            }
        }

        // all NKG blocks of this layer rendezvous (single atomic + load-poll)
        __threadfence();
        __syncthreads();
        if (t == 0) {
            atomicAdd(&g_done[l], 1);
            spin_ge(&g_done[l], (E + 1) * NKG);
        }
        __syncthreads();
        __threadfence();

        {
            const int n4 = cnt * (RNK / 4);
            const int base4 = off * (RNK / 4);
            const float4* pp = (const float4*)g_partial;
            const int stride4 = BB * RNK / 4;
            for (int i = kg * TPB + t; i < n4; i += NKG * TPB) {
                float4 s = __ldcg(pp + base4 + i);
                #pragma unroll
                for (int kc = 1; kc < NKG; kc++) {
                    float4 q = __ldcg(pp + (size_t)kc * stride4 + base4 + i);
                    s.x += q.x; s.y += q.y; s.z += q.z; s.w += q.w;
                }
                ((float4*)g_proj)[base4 + i] = s;
            }
        }
        __threadfence();
        __syncthreads();
        if (t == 0) {
            int r = atomicAdd(&g_rdone[l], 1);
            if (r == (E + 1) * NKG - 1) atomicExch(&g_flag[l], E + 1);
        }
    } else {
        // ================= OUT =================
        int hb = sub;
        int h0 = hb * HT;
        uint32_t* su = smem;               // [HT][STU]  17.4 KB
        uint32_t* sp = smem + HT * STU;    // [MT][STU]  17.4 KB
        uint32_t su_b = (uint32_t)__cvta_generic_to_shared(su);
        uint32_t sp_b = (uint32_t)__cvta_generic_to_shared(sp);

        // stage u tile (independent of everything), overlaps the spin
        #pragma unroll
        for (int i = 0; i < (HT * 16) / TPB; i++) {         // 4 iters
            int idxx = t + i * TPB;
            int row = idxx >> 4, c4 = idxx & 15;
            cpa16(su_b + (row * STU + c4 * 4) * 4,
                  u + ((size_t)l * HH + h0 + row) * RNK + c4 * 4, 16);
        }
        cpa_commit();

        // wait for this layer's proj+reduce (load-poll; implies sort done)
        if (t == 0) spin_ge(&g_flag[l], E + 1);
        __syncthreads();
        __threadfence();

        int off = g_offsets[l];
        int cnt = g_offsets[l + 1] - off;

        for (int m0 = 0; m0 < cnt; m0 += MT) {
            int nc = min(MT, cnt - m0);
            if (m0 > 0) __syncthreads();
            #pragma unroll
            for (int i = 0; i < (MT * 16) / TPB; i++) {     // 4 iters
                int idxx = t + i * TPB;
                int row = idxx >> 4, c4 = idxx & 15;
                const float* src = g_proj;
                uint32_t szb = 0;
                if (row < nc) {
                    src = g_proj + (size_t)(off + m0 + row) * RNK + c4 * 4;
                    szb = 16;
                }
                cpa16(sp_b + (row * STU + c4 * 4) * 4, src, szb);
            }
            cpa_commit();

            // prefetch epilogue z into registers BEFORE the wait — its DRAM
            // latency overlaps the cp.async completion instead of following it
            int    gsr[2][2];
            float2 zpre[2][2][2];
            #pragma unroll
            for (int mt = 0; mt < 2; mt++)
                #pragma unroll
                for (int half = 0; half < 2; half++) {
                    int rr = wm * 32 + mt * 16 + gid + half * 8;
                    int rid = (rr < nc) ? rr : 0;
                    int gs = g_sorted[off + m0 + rid];
                    gsr[mt][half] = gs;
                    const float* zrow = z + (size_t)gs * HH + h0;
                    #pragma unroll
                    for (int j = 0; j < 2; j++)
                        zpre[mt][half][j] = *(const float2*)&zrow[wn * 16 + j * 8 + 2 * tig];
                }

            cpa_wait0();   // also covers u on first iteration
            __syncthreads();

            float acc[2][2][4];
            #pragma unroll
            for (int mt = 0; mt < 2; mt++)
                #pragma unroll
                for (int j = 0; j < 2; j++)
                    #pragma unroll
                    for (int q = 0; q < 4; q++) acc[mt][j][q] = 0.0f;

            #pragma unroll
            for (int ks = 0; ks < 8; ks++) {
                int kb = ks * 8 + tig;
                uint32_t b0[2], b1[2];
                #pragma unroll
                for (int j = 0; j < 2; j++) {
                    int n = wn * 16 + j * 8 + gid;
                    b0[j] = su[n * STU + kb];
                    b1[j] = su[n * STU + kb + 4];
                }
                #pragma unroll
                for (int mt = 0; mt < 2; mt++) {
                    const uint32_t* spr = sp + (wm * 32 + mt * 16 + gid) * STU;
                    uint32_t a0 = spr[kb];
                    uint32_t a1 = spr[8 * STU + kb];
                    uint32_t a2 = spr[kb + 4];
                    uint32_t a3 = spr[8 * STU + kb + 4];
                    #pragma unroll
                    for (int j = 0; j < 2; j++)
                        MMA_TF32(acc[mt][j][0], acc[mt][j][1], acc[mt][j][2], acc[mt][j][3],
                                 a0, a1, a2, a3, b0[j], b1[j]);
                }
            }

            // epilogue: out = z(regs) + delta
            #pragma unroll
            for (int mt = 0; mt < 2; mt++) {
                #pragma unroll
                for (int half = 0; half < 2; half++) {
                    int rr = wm * 32 + mt * 16 + gid + half * 8;
                    if (rr < nc) {
                        float* orow = out + (size_t)gsr[mt][half] * HH + h0;
                        #pragma unroll
                        for (int j = 0; j < 2; j++) {
                            int col = wn * 16 + j * 8 + 2 * tig;
                            float2 zz = zpre[mt][half][j];
                            *(float2*)&orow[col] =
                                make_float2(zz.x + acc[mt][j][half * 2 + 0],
                                            zz.y + acc[mt][j][half * 2 + 1]);
                        }
                    }
                }
            }
        }
    }

    // replay epilogue: last block of this replay advances the epoch
    __syncthreads();
    if (t == 0) {
        int r = atomicAdd(&g_allcnt, 1);
        if (r == (E + 1) * GRID_TOTAL - 1) atomicExch(&g_epoch, E + 1);
    }
}

// ---------------------------------------------------------------------------
extern "C" void kernel_launch(void* const* d_in, const int* in_sizes, int n_in,
                              void* d_out, int out_size) {
    const float* z   = (const float*)d_in[0];
    const int*   ids = (const int*)  d_in[1];
    const float* u   = (const float*)d_in[2];
    const float* v   = (const float*)d_in[3];
    float*       out = (float*)d_out;

    const int fused_smem = (MT * STZ + KCH * STB) * 4;   // 35.8 KB (covers sort's 33 KB)
    cudaFuncSetAttribute(fused_kernel, cudaFuncAttributeMaxDynamicSharedMemorySize, fused_smem);

    fused_kernel<<<GRID_TOTAL, TPB, fused_smem>>>(z, ids, v, u, out);
}

// round 15
// speedup vs baseline: 1.6775x; 1.6775x over previous
#include <cuda_runtime.h>
#include <cstdint>

// Problem constants
#define BB   2048
#define HH   2048
#define RNK  64
#define LL   32

#define NKG  8           // split-K groups (k per proj block = 256)
#define KCH  256
#define KST  64          // K per pipeline stage
#define MT   64          // M tile (samples)
#define HT   64          // h tile for GEMM2
#define TPB  256         // 8 warps everywhere
#define STZ  68          // sample-major tiles stride (68 mod 32 == 4)
#define STB  72          // k-major v tile stride     (72 mod 32 == 8)
#define STU  68          // n-major u/proj stride     (68 mod 32 == 4)

#define ZW   (MT * STZ)        // words per z stage buffer (4352)
#define VW   (KST * STB)       // words per v stage buffer (4608)
#define BUFW (ZW + VW)         // 8960 words = 35.8 KB; x2 buffers = 71.7 KB

#define PROJ_BLOCKS (NKG * LL)        // 256
#define OUT_BLOCKS  ((HH / HT) * LL)  // 1024
#define GRID_TOTAL  (1 + PROJ_BLOCKS + OUT_BLOCKS)  // 1281

// Scratch (device globals — no allocations allowed).
// Synchronization state is MONOTONIC across graph replays (epoch-versioned).
__device__ int    g_offsets[LL + 1];
__device__ int    g_sorted[BB];
__device__ float  g_partial[(size_t)NKG * BB * RNK];   // 4 MB, by sorted pos
__device__ float  g_proj[(size_t)BB * RNK];            // by sorted pos
__device__ int    g_epoch    = 0;
__device__ int    g_sortflag = 0;
__device__ int    g_done[LL]  = {};    // (E+1)*NKG when layer proj done
__device__ int    g_rdone[LL] = {};
__device__ int    g_flag[LL]  = {};    // E+1 when layer proj+reduce done
__device__ int    g_allcnt   = 0;

#define MMA_TF32(c0,c1,c2,c3,a0,a1,a2,a3,b0,b1)                         \
    asm("mma.sync.aligned.m16n8k8.row.col.f32.tf32.tf32.f32 "           \
        "{%0,%1,%2,%3}, {%4,%5,%6,%7}, {%8,%9}, {%0,%1,%2,%3};"         \
        : "+f"(c0), "+f"(c1), "+f"(c2), "+f"(c3)                        \
        : "r"(a0), "r"(a1), "r"(a2), "r"(a3), "r"(b0), "r"(b1))

__device__ __forceinline__ void cpa16(uint32_t dst, const void* src, uint32_t sz) {
    asm volatile("cp.async.cg.shared.global [%0], [%1], 16, %2;"
                 :: "r"(dst), "l"(src), "r"(sz));
}
__device__ __forceinline__ void cpa_commit() { asm volatile("cp.async.commit_group;"); }
__device__ __forceinline__ void cpa_wait0()  { asm volatile("cp.async.wait_group 0;"); }
__device__ __forceinline__ void cpa_wait1()  { asm volatile("cp.async.wait_group 1;"); }

// Low-contention spin: plain L2 load (no RMW), growing backoff.
__device__ __forceinline__ void spin_ge(const int* addr, int target) {
    unsigned ns = 64;
    while (__ldcg(addr) < target) {
        __nanosleep(ns);
        if (ns < 1024) ns <<= 1;
    }
}

// ---------------------------------------------------------------------------
// Single fused kernel, R13 ordering (sort | all proj | all out):
//   bid 0            : sort
//   bid in [1,257)   : proj (l = (bid-1)/8, kg = (bid-1)%8), KCH=256 pipelined
//   bid in [257,1281): out  (l = (bid-257)/32, hb = (bid-257)%32)
// 257 sort+proj blocks < one wave -> whole proj phase runs concurrently.
// ---------------------------------------------------------------------------
__global__ __launch_bounds__(TPB, 3) void fused_kernel(const float* __restrict__ z,
                                                       const int*   __restrict__ ids,
                                                       const float* __restrict__ v,
                                                       const float* __restrict__ u,
                                                       float* __restrict__ out) {
    extern __shared__ __align__(16) uint32_t smem[];
    __shared__ int s_E;

    int t = threadIdx.x, lane = t & 31, w = t >> 5;
    int gid = lane >> 2, tig = lane & 3;
    int wm = w & 1, wn = w >> 1;           // 8 warps: m32 x n16
    int bid = blockIdx.x;

    if (t == 0) s_E = __ldcg(&g_epoch);
    __syncthreads();
    const int E = s_E;

    if (bid == 0) {
        // ================= SORT =================
        int* A = (int*)smem;               // [LL*256] 32 KB
        int* S = A + LL * 256;             // [256]
        #pragma unroll
        for (int ll2 = 0; ll2 < LL; ll2++) A[ll2 * 256 + t] = 0;
        int seg = t * (BB / 256);
        #pragma unroll
        for (int i = 0; i < BB / 256; i++) {
            int lid = ids[seg + i];
            A[lid * 256 + t]++;
        }
        __syncthreads();
        int base = t * 32;
        int sum = 0;
        #pragma unroll
        for (int j = 0; j < 32; j++) { int x = A[base + j]; A[base + j] = sum; sum += x; }
        S[t] = sum;
        int mysum = sum;
        __syncthreads();
        for (int d = 1; d < 256; d <<= 1) {
            int add = (t >= d) ? S[t - d] : 0;
            __syncthreads();
            S[t] += add;
            __syncthreads();
        }
        int excl = S[t] - mysum;
        #pragma unroll
        for (int j = 0; j < 32; j++) A[base + j] += excl;
        __syncthreads();
        if (t < LL) g_offsets[t] = A[t * 256];
        if (t == 0) g_offsets[LL] = BB;
        #pragma unroll
        for (int i = 0; i < BB / 256; i++) {
            int s = seg + i;
            int lid = ids[s];
            int p = A[lid * 256 + t];
            A[lid * 256 + t] = p + 1;
            g_sorted[p] = s;
        }
        __threadfence();
        __syncthreads();
        if (t == 0) atomicExch(&g_sortflag, E + 1);
    } else if (bid <= PROJ_BLOCKS) {
        // ================= PROJ (pipelined, KCH=256 in 4 stages) ==========
        int pb = bid - 1;
        int l = pb >> 3, kg = pb & 7;
        uint32_t sb = (uint32_t)__cvta_generic_to_shared(smem);

        // stage only the v-halves of both buffers BEFORE the sort spin
        auto stage_v = [&](int it) {
            int k0 = kg * KCH + (it & 3) * KST;
            uint32_t vb = sb + (uint32_t)(it & 1) * BUFW * 4 + ZW * 4;
            #pragma unroll
            for (int i = 0; i < (KST * 16) / TPB; i++) {    // 4 iters
                int idx = t + i * TPB;
                int row = idx >> 4, c4 = idx & 15;
                cpa16(vb + (row * STB + c4 * 4) * 4,
                      v + ((size_t)l * HH + k0 + row) * RNK + c4 * 4, 16);
            }
            cpa_commit();
        };
        stage_v(0);
        stage_v(1);

        if (t == 0) spin_ge(&g_sortflag, E + 1);
        __syncthreads();
        __threadfence();

        int off = g_offsets[l];
        int cnt = g_offsets[l + 1] - off;
        int nm = (cnt + MT - 1) / MT;
        int total = nm * 4;

        auto stage_z = [&](int it) {
            int m0 = (it >> 2) * MT;
            int nc = min(MT, cnt - m0);
            int k0 = kg * KCH + (it & 3) * KST;
            uint32_t zb = sb + (uint32_t)(it & 1) * BUFW * 4;
            #pragma unroll
            for (int i = 0; i < (MT * 16) / TPB; i++) {     // 4 iters
                int idx = t + i * TPB;
                int row = idx >> 4, c4 = idx & 15;
                const float* src = z;
                uint32_t szb = 0;
                if (row < nc) {
                    int gs = g_sorted[off + m0 + row];
                    src = z + (size_t)gs * HH + k0 + c4 * 4;
                    szb = 16;
                }
                cpa16(zb + (row * STZ + c4 * 4) * 4, src, szb);
            }
            cpa_commit();
        };
        auto stage_full = [&](int it) {     // z + v, single commit group
            int m0 = (it >> 2) * MT;
            int nc = min(MT, cnt - m0);
            int k0 = kg * KCH + (it & 3) * KST;
            uint32_t zb = sb + (uint32_t)(it & 1) * BUFW * 4;
            uint32_t vb = zb + ZW * 4;
            #pragma unroll
            for (int i = 0; i < (MT * 16) / TPB; i++) {
                int idx = t + i * TPB;
                int row = idx >> 4, c4 = idx & 15;
                const float* src = z;
                uint32_t szb = 0;
                if (row < nc) {
                    int gs = g_sorted[off + m0 + row];
                    src = z + (size_t)gs * HH + k0 + c4 * 4;
                    szb = 16;
                }
                cpa16(zb + (row * STZ + c4 * 4) * 4, src, szb);
            }
            #pragma unroll
            for (int i = 0; i < (KST * 16) / TPB; i++) {
                int idx = t + i * TPB;
                int row = idx >> 4, c4 = idx & 15;
                cpa16(vb + (row * STB + c4 * 4) * 4,
                      v + ((size_t)l * HH + k0 + row) * RNK + c4 * 4, 16);
            }
            cpa_commit();
        };

        if (total > 0) {
            stage_z(0);
            stage_z(1);   // total >= 4 whenever cnt > 0

            float acc[2][2][4];
            for (int it = 0; it < total; it++) {
                int kk = it & 3;
                if (kk == 0) {
                    #pragma unroll
                    for (int mt = 0; mt < 2; mt++)
                        #pragma unroll
                        for (int j = 0; j < 2; j++)
                            #pragma unroll
                            for (int q = 0; q < 4; q++) acc[mt][j][q] = 0.0f;
                }
                if (it + 1 < total) cpa_wait1(); else cpa_wait0();
                __syncthreads();

                const uint32_t* zt = smem + (it & 1) * BUFW;
                const uint32_t* vt = zt + ZW;

                #pragma unroll
                for (int ks = 0; ks < KST / 8; ks++) {      // 8 iters
                    int kb = ks * 8 + tig;
                    uint32_t b0[2], b1[2];
                    #pragma unroll
                    for (int j = 0; j < 2; j++) {
                        int n = wn * 16 + j * 8 + gid;
                        b0[j] = vt[kb * STB + n];
                        b1[j] = vt[(kb + 4) * STB + n];
                    }
                    #pragma unroll
                    for (int mt = 0; mt < 2; mt++) {
                        const uint32_t* zr = zt + (wm * 32 + mt * 16 + gid) * STZ;
                        uint32_t a0 = zr[kb];
                        uint32_t a1 = zr[8 * STZ + kb];
                        uint32_t a2 = zr[kb + 4];
                        uint32_t a3 = zr[8 * STZ + kb + 4];
                        #pragma unroll
                        for (int j = 0; j < 2; j++)
                            MMA_TF32(acc[mt][j][0], acc[mt][j][1], acc[mt][j][2], acc[mt][j][3],
                                     a0, a1, a2, a3, b0[j], b1[j]);
                    }
                }
                __syncthreads();
                if (it + 2 < total) stage_full(it + 2);

                if (kk == 3) {
                    int m0 = (it >> 2) * MT;
                    int nc = min(MT, cnt - m0);
                    float* pb2 = g_partial + (size_t)kg * BB * RNK;
                    #pragma unroll
                    for (int mt = 0; mt < 2; mt++) {
                        int rbase = wm * 32 + mt * 16 + gid;
                        #pragma unroll
                        for (int j = 0; j < 2; j++) {
                            int col = wn * 16 + j * 8 + 2 * tig;
                            if (rbase < nc)
                                *(float2*)&pb2[(size_t)(off + m0 + rbase) * RNK + col] =
                                    make_float2(acc[mt][j][0], acc[mt][j][1]);
                            if (rbase + 8 < nc)
                                *(float2*)&pb2[(size_t)(off + m0 + rbase + 8) * RNK + col] =
                                    make_float2(acc[mt][j][2], acc[mt][j][3]);
                        }
                    }
                }
            }
        } else {
            cpa_wait0();   // drain prestaged v
        }

        // rendezvous of the NKG blocks of this layer, then cooperative reduce
        __threadfence();
        __syncthreads();
        if (t == 0) {
            atomicAdd(&g_done[l], 1);
            spin_ge(&g_done[l], (E + 1) * NKG);
        }
        __syncthreads();
        __threadfence();

        {
            const int n4 = cnt * (RNK / 4);
            const int base4 = off * (RNK / 4);
            const float4* pp = (const float4*)g_partial;
            const int stride4 = BB * RNK / 4;
            for (int i = kg * TPB + t; i < n4; i += NKG * TPB) {
                float4 s = __ldcg(pp + base4 + i);
                #pragma unroll
                for (int kc = 1; kc < NKG; kc++) {
                    float4 q = __ldcg(pp + (size_t)kc * stride4 + base4 + i);
                    s.x += q.x; s.y += q.y; s.z += q.z; s.w += q.w;
                }
                ((float4*)g_proj)[base4 + i] = s;
            }
        }
        __threadfence();
        __syncthreads();
        if (t == 0) {
            int r = atomicAdd(&g_rdone[l], 1);
            if (r == (E + 1) * NKG - 1) atomicExch(&g_flag[l], E + 1);
        }
    } else {
        // ================= OUT =================
        int ob = bid - 1 - PROJ_BLOCKS;
        int l = ob >> 5, hb = ob & 31;
        int h0 = hb * HT;
        uint32_t* su = smem;               // [HT][STU]  17.4 KB
        uint32_t* sp = smem + HT * STU;    // [MT][STU]  17.4 KB
        uint32_t su_b = (uint32_t)__cvta_generic_to_shared(su);
        uint32_t sp_b = (uint32_t)__cvta_generic_to_shared(sp);

        // stage u tile (independent of everything), overlaps the spin
        #pragma unroll
        for (int i = 0; i < (HT * 16) / TPB; i++) {         // 4 iters
            int idxx = t + i * TPB;
            int row = idxx >> 4, c4 = idxx & 15;
            cpa16(su_b + (row * STU + c4 * 4) * 4,
                  u + ((size_t)l * HH + h0 + row) * RNK + c4 * 4, 16);
        }
        cpa_commit();

        // wait for this layer's proj+reduce (load-poll; implies sort done)
        if (t == 0) spin_ge(&g_flag[l], E + 1);
        __syncthreads();
        __threadfence();

        int off = g_offsets[l];
        int cnt = g_offsets[l + 1] - off;

        for (int m0 = 0; m0 < cnt; m0 += MT) {
            int nc = min(MT, cnt - m0);
            if (m0 > 0) __syncthreads();
            #pragma unroll
            for (int i = 0; i < (MT * 16) / TPB; i++) {     // 4 iters
                int idxx = t + i * TPB;
                int row = idxx >> 4, c4 = idxx & 15;
                const float* src = g_proj;
                uint32_t szb = 0;
                if (row < nc) {
                    src = g_proj + (size_t)(off + m0 + row) * RNK + c4 * 4;
                    szb = 16;
                }
                cpa16(sp_b + (row * STU + c4 * 4) * 4, src, szb);
            }
            cpa_commit();

            // prefetch epilogue z into registers BEFORE the wait
            int    gsr[2][2];
            float2 zpre[2][2][2];
            #pragma unroll
            for (int mt = 0; mt < 2; mt++)
                #pragma unroll
                for (int half = 0; half < 2; half++) {
                    int rr = wm * 32 + mt * 16 + gid + half * 8;
                    int rid = (rr < nc) ? rr : 0;
                    int gs = g_sorted[off + m0 + rid];
                    gsr[mt][half] = gs;
                    const float* zrow = z + (size_t)gs * HH + h0;
                    #pragma unroll
                    for (int j = 0; j < 2; j++)
                        zpre[mt][half][j] = *(const float2*)&zrow[wn * 16 + j * 8 + 2 * tig];
                }

            cpa_wait0();   // also covers u on first iteration
            __syncthreads();

            float acc[2][2][4];
            #pragma unroll
            for (int mt = 0; mt < 2; mt++)
                #pragma unroll
                for (int j = 0; j < 2; j++)
                    #pragma unroll
                    for (int q = 0; q < 4; q++) acc[mt][j][q] = 0.0f;

            #pragma unroll
            for (int ks = 0; ks < 8; ks++) {
                int kb = ks * 8 + tig;
                uint32_t b0[2], b1[2];
                #pragma unroll
                for (int j = 0; j < 2; j++) {
                    int n = wn * 16 + j * 8 + gid;
                    b0[j] = su[n * STU + kb];
                    b1[j] = su[n * STU + kb + 4];
                }
                #pragma unroll
                for (int mt = 0; mt < 2; mt++) {
                    const uint32_t* spr = sp + (wm * 32 + mt * 16 + gid) * STU;
                    uint32_t a0 = spr[kb];
                    uint32_t a1 = spr[8 * STU + kb];
                    uint32_t a2 = spr[kb + 4];
                    uint32_t a3 = spr[8 * STU + kb + 4];
                    #pragma unroll
                    for (int j = 0; j < 2; j++)
                        MMA_TF32(acc[mt][j][0], acc[mt][j][1], acc[mt][j][2], acc[mt][j][3],
                                 a0, a1, a2, a3, b0[j], b1[j]);
                }
            }

            // epilogue: out = z(regs) + delta
            #pragma unroll
            for (int mt = 0; mt < 2; mt++) {
                #pragma unroll
                for (int half = 0; half < 2; half++) {
                    int rr = wm * 32 + mt * 16 + gid + half * 8;
                    if (rr < nc) {
                        float* orow = out + (size_t)gsr[mt][half] * HH + h0;
                        #pragma unroll
                        for (int j = 0; j < 2; j++) {
                            int col = wn * 16 + j * 8 + 2 * tig;
                            float2 zz = zpre[mt][half][j];
                            *(float2*)&orow[col] =
                                make_float2(zz.x + acc[mt][j][half * 2 + 0],
                                            zz.y + acc[mt][j][half * 2 + 1]);
                        }
                    }
                }
            }
        }
    }

    // replay epilogue: last block of this replay advances the epoch
    __syncthreads();
    if (t == 0) {
        int r = atomicAdd(&g_allcnt, 1);
        if (r == (E + 1) * GRID_TOTAL - 1) atomicExch(&g_epoch, E + 1);
    }
}

// ---------------------------------------------------------------------------
extern "C" void kernel_launch(void* const* d_in, const int* in_sizes, int n_in,
                              void* d_out, int out_size) {
    const float* z   = (const float*)d_in[0];
    const int*   ids = (const int*)  d_in[1];
    const float* u   = (const float*)d_in[2];
    const float* v   = (const float*)d_in[3];
    float*       out = (float*)d_out;

    const int fused_smem = 2 * BUFW * 4;   // 71.7 KB (covers sort 33 KB, out 34.8 KB)
    cudaFuncSetAttribute(fused_kernel, cudaFuncAttributeMaxDynamicSharedMemorySize, fused_smem);

    fused_kernel<<<GRID_TOTAL, TPB, fused_smem>>>(z, ids, v, u, out);
}